// round 6
// baseline (speedup 1.0000x reference)
#include <cuda_runtime.h>

#define INPUT_SIZE     32768
#define NUM_COLS       4096
#define NUM_ACTIVE     82
#define THREADS        256
#define ROWS_PER_BLOCK 4
#define NBLOCKS        (NUM_COLS / ROWS_PER_BLOCK)   // 1024 -> single wave
#define COMPACT_BLOCKS 32
#define SMEM_IDX_CAP   4096

// Scratch (allocation-free rule). Zero-initialized at module load; reset by
// topk_kernel each call so graph replays stay deterministic.
__device__ int          g_count;
__device__ volatile int g_ready;
__device__ int          g_indices[INPUT_SIZE];
__device__ float        g_boosted[NUM_COLS];

// ---------------------------------------------------------------------------
// Fused kernel: blocks 0..31 compact the on-bit indices of input_vector
// (atomic slice reservation -> order nondeterministic, output invariant since
// all downstream sums are exact small-integer commutative reductions), all
// blocks then spin on a flag and gather 4 rows each (16 load streams/thread).
// 1024 blocks <= 1184 concurrent capacity -> whole grid resident, no deadlock,
// no wave-2 tail.
// ---------------------------------------------------------------------------
__global__ __launch_bounds__(THREADS, 8)
void fused_kernel(const float* __restrict__ in,
                  const float* __restrict__ conn,
                  const float* __restrict__ boost) {
    __shared__ int   sidx[SMEM_IDX_CAP];
    __shared__ int   s_n;
    __shared__ int   wsum[8];
    __shared__ int   sbase;
    __shared__ float wred[32];

    const int tid  = threadIdx.x;
    const int bid  = blockIdx.x;
    const int lane = tid & 31;
    const int warp = tid >> 5;

    // ---- Phase A: compaction (blocks 0..31) ----
    if (bid < COMPACT_BLOCKS) {
        const int base = bid * 1024 + tid * 4;
        float4 q = reinterpret_cast<const float4*>(in)[base >> 2];
        float v[4] = {q.x, q.y, q.z, q.w};
        int cnt = 0;
#pragma unroll
        for (int i = 0; i < 4; i++) cnt += (v[i] != 0.0f) ? 1 : 0;

        int x = cnt;
#pragma unroll
        for (int d = 1; d < 32; d <<= 1) {
            int y = __shfl_up_sync(0xffffffffu, x, d);
            if (lane >= d) x += y;                    // inclusive warp scan
        }
        if (lane == 31) wsum[warp] = x;
        __syncthreads();
        if (tid == 0) {
            int acc = 0;
#pragma unroll
            for (int w = 0; w < 8; w++) { int c = wsum[w]; wsum[w] = acc; acc += c; }
            sbase = atomicAdd(&g_count, acc);         // reserve output slice
        }
        __syncthreads();
        int off = sbase + wsum[warp] + (x - cnt);
#pragma unroll
        for (int i = 0; i < 4; i++)
            if (v[i] != 0.0f) g_indices[off++] = base + i;
        __threadfence();
        if (tid == 0) atomicAdd((int*)&g_ready, 1);
    }

    // ---- Wait for compaction (flag in L2, coherent) ----
    if (tid == 0) {
        while (*(volatile int*)&g_ready < COMPACT_BLOCKS) __nanosleep(64);
        __threadfence();
        s_n = *(volatile int*)&g_count;
    }
    __syncthreads();
    const int n = s_n;

    // ---- Stage index list into SMEM ----
    const int n_s = (n < SMEM_IDX_CAP) ? n : SMEM_IDX_CAP;
    for (int k = tid; k < n_s; k += THREADS) sidx[k] = g_indices[k];
    __syncthreads();

    // ---- Phase B: gather 4 rows, 4-deep idx unroll -> 16 streams ----
    const int r = bid * ROWS_PER_BLOCK;
    const float* __restrict__ row0 = conn + (size_t)r * INPUT_SIZE;
    const float* __restrict__ row1 = row0 + INPUT_SIZE;
    const float* __restrict__ row2 = row1 + INPUT_SIZE;
    const float* __restrict__ row3 = row2 + INPUT_SIZE;

    float a[4] = {0.f, 0.f, 0.f, 0.f};
    float b[4] = {0.f, 0.f, 0.f, 0.f};
    float c_[4] = {0.f, 0.f, 0.f, 0.f};
    float d_[4] = {0.f, 0.f, 0.f, 0.f};
    int k = tid;
    for (; k + 3 * THREADS < n_s; k += 4 * THREADS) {
        int i0 = sidx[k];
        int i1 = sidx[k +     THREADS];
        int i2 = sidx[k + 2 * THREADS];
        int i3 = sidx[k + 3 * THREADS];
        a[0] += __ldcs(row0 + i0);  b[0] += __ldcs(row1 + i0);
        c_[0] += __ldcs(row2 + i0); d_[0] += __ldcs(row3 + i0);
        a[1] += __ldcs(row0 + i1);  b[1] += __ldcs(row1 + i1);
        c_[1] += __ldcs(row2 + i1); d_[1] += __ldcs(row3 + i1);
        a[2] += __ldcs(row0 + i2);  b[2] += __ldcs(row1 + i2);
        c_[2] += __ldcs(row2 + i2); d_[2] += __ldcs(row3 + i2);
        a[3] += __ldcs(row0 + i3);  b[3] += __ldcs(row1 + i3);
        c_[3] += __ldcs(row2 + i3); d_[3] += __ldcs(row3 + i3);
    }
    for (; k < n_s; k += THREADS) {
        int i = sidx[k];
        a[0] += __ldcs(row0 + i);  b[0] += __ldcs(row1 + i);
        c_[0] += __ldcs(row2 + i); d_[0] += __ldcs(row3 + i);
    }
    for (int k2 = SMEM_IDX_CAP + tid; k2 < n; k2 += THREADS) {  // safety tail
        int i = g_indices[k2];
        a[0] += __ldcs(row0 + i);  b[0] += __ldcs(row1 + i);
        c_[0] += __ldcs(row2 + i); d_[0] += __ldcs(row3 + i);
    }
    float sa = (a[0] + a[1]) + (a[2] + a[3]);
    float sb = (b[0] + b[1]) + (b[2] + b[3]);
    float sc = (c_[0] + c_[1]) + (c_[2] + c_[3]);
    float sd = (d_[0] + d_[1]) + (d_[2] + d_[3]);

    // ---- Block reduce all four rows ----
#pragma unroll
    for (int dd = 16; dd; dd >>= 1) {
        sa += __shfl_down_sync(0xffffffffu, sa, dd);
        sb += __shfl_down_sync(0xffffffffu, sb, dd);
        sc += __shfl_down_sync(0xffffffffu, sc, dd);
        sd += __shfl_down_sync(0xffffffffu, sd, dd);
    }
    if (lane == 0) {
        wred[warp]      = sa;  wred[8 + warp]  = sb;
        wred[16 + warp] = sc;  wred[24 + warp] = sd;
    }
    __syncthreads();
    if (tid < 4) {
        float t = 0.f;
#pragma unroll
        for (int w = 0; w < 8; w++) t += wred[tid * 8 + w];
        g_boosted[r + tid] = t * __ldg(&boost[r + tid]);
    }
}

// ---------------------------------------------------------------------------
// Stable top-k by exact rank counting on u64 keys.
//   key(j) = (float_bits(v_j) << 12) | (4095 - j)
// Values are nonneg -> unsigned bit order == value order; appended inverted
// index makes keys distinct and encodes jax.lax.top_k's tie-break exactly
// (value desc, index asc). Column wins iff #(key_j > key_c) < NUM_ACTIVE.
// 128 blocks (single wave) x 8 warps x 4 columns; keys staged in SMEM once.
// Also resets scratch flags for the next graph replay.
// ---------------------------------------------------------------------------
__global__ __launch_bounds__(256)
void topk_kernel(float* __restrict__ out) {
    if (blockIdx.x == 0 && threadIdx.x == 0) { g_count = 0; g_ready = 0; }

    __shared__ unsigned long long skey[NUM_COLS];   // 32KB
    const int tid  = threadIdx.x;
    const int lane = tid & 31;
    const int warp = tid >> 5;

    for (int j = tid; j < NUM_COLS; j += 256) {
        unsigned int bits = __float_as_uint(g_boosted[j]);
        skey[j] = ((unsigned long long)bits << 12) | (unsigned)(4095 - j);
    }
    __syncthreads();

    const int cbase = blockIdx.x * 32 + warp * 4;
    const unsigned long long k0 = skey[cbase];
    const unsigned long long k1 = skey[cbase + 1];
    const unsigned long long k2 = skey[cbase + 2];
    const unsigned long long k3 = skey[cbase + 3];

    int c0 = 0, c1 = 0, c2 = 0, c3 = 0;
#pragma unroll 4
    for (int j = lane; j < NUM_COLS; j += 32) {
        unsigned long long kj = skey[j];
        c0 += (kj > k0) ? 1 : 0;
        c1 += (kj > k1) ? 1 : 0;
        c2 += (kj > k2) ? 1 : 0;
        c3 += (kj > k3) ? 1 : 0;
    }
    // Pack two 16-bit counts per int -> 2 shfl reductions instead of 4.
    int p01 = c0 | (c1 << 16);
    int p23 = c2 | (c3 << 16);
#pragma unroll
    for (int d = 16; d; d >>= 1) {
        p01 += __shfl_down_sync(0xffffffffu, p01, d);
        p23 += __shfl_down_sync(0xffffffffu, p23, d);
    }
    if (lane == 0) {
        int cnt[4] = { p01 & 0xffff, p01 >> 16, p23 & 0xffff, p23 >> 16 };
#pragma unroll
        for (int q = 0; q < 4; q++) {
            const int c = cbase + q;
            const bool win = (cnt[q] < NUM_ACTIVE);
            const float vc = g_boosted[c];
            out[c]            = win ? 1.0f : 0.0f;
            out[NUM_COLS + c] = win ? vc   : 0.0f;
        }
    }
}

// ---------------------------------------------------------------------------
extern "C" void kernel_launch(void* const* d_in, const int* in_sizes, int n_in,
                              void* d_out, int out_size) {
    const float* inp   = nullptr;
    const float* conn  = nullptr;
    const float* boost = nullptr;
    for (int i = 0; i < n_in; i++) {
        if (in_sizes[i] == INPUT_SIZE)      inp   = (const float*)d_in[i];
        else if (in_sizes[i] == NUM_COLS)   boost = (const float*)d_in[i];
        else                                conn  = (const float*)d_in[i];
    }
    float* out = (float*)d_out;
    (void)out_size; (void)n_in;

    fused_kernel<<<NBLOCKS, THREADS>>>(inp, conn, boost);
    topk_kernel<<<NUM_COLS / 32, 256>>>(out);
}

// round 7
// speedup vs baseline: 1.0805x; 1.0805x over previous
#include <cuda_runtime.h>

#define INPUT_SIZE     32768
#define NUM_COLS       4096
#define NUM_ACTIVE     82
#define THREADS        256
#define ROWS_PER_BLOCK 4
#define NBLOCKS        (NUM_COLS / ROWS_PER_BLOCK)   // 1024
#define COMPACT_BLOCKS 32
#define SMEM_IDX_CAP   4096
#define HIST_BINS      4096

// Scratch (allocation-free rule). Zero-initialized at module load; reset by
// the elected block at the end of each call -> graph replays deterministic.
__device__ int          g_count;
__device__ volatile int g_ready;
__device__ int          g_done;
__device__ int          g_indices[INPUT_SIZE];
__device__ float        g_boosted[NUM_COLS];

// ---------------------------------------------------------------------------
// ONE fused kernel:
//   Phase A (blocks 0..31): compact on-bit indices of input_vector
//     (atomic slice reservation; order nondeterministic, output invariant
//      since all downstream sums are exact small-integer commutative sums).
//   Phase B (all blocks): spin on flag, stage indices in SMEM, gather 4 rows
//     each with 16 independent load streams, block-reduce, write g_boosted.
//   Phase C (last-finishing block): histogram top-k over the 4096 exact
//     integer overlaps: find threshold T and residue R, stable tie-break by
//     column index (== jax.lax.top_k order), write both output segments,
//     reset scratch.
// ---------------------------------------------------------------------------
__global__ __launch_bounds__(THREADS)
void fused_kernel(const float* __restrict__ in,
                  const float* __restrict__ conn,
                  const float* __restrict__ boost,
                  float* __restrict__ out) {
    __shared__ int   buf[HIST_BINS];     // phase B: sidx; phase C: histogram
    __shared__ int   s_n;
    __shared__ int   wsum[8];
    __shared__ int   sbase;
    __shared__ float wred[32];
    __shared__ int   s_elected;
    __shared__ int   sT, sR;
    __shared__ int   scan_tmp[THREADS];

    const int tid  = threadIdx.x;
    const int bid  = blockIdx.x;
    const int lane = tid & 31;
    const int warp = tid >> 5;

    // ================= Phase A: compaction (blocks 0..31) =================
    if (bid < COMPACT_BLOCKS) {
        const int base = bid * 1024 + tid * 4;
        float4 q = reinterpret_cast<const float4*>(in)[base >> 2];
        float v[4] = {q.x, q.y, q.z, q.w};
        int cnt = 0;
#pragma unroll
        for (int i = 0; i < 4; i++) cnt += (v[i] != 0.0f) ? 1 : 0;

        int x = cnt;
#pragma unroll
        for (int d = 1; d < 32; d <<= 1) {
            int y = __shfl_up_sync(0xffffffffu, x, d);
            if (lane >= d) x += y;                    // inclusive warp scan
        }
        if (lane == 31) wsum[warp] = x;
        __syncthreads();
        if (tid == 0) {
            int acc = 0;
#pragma unroll
            for (int w = 0; w < 8; w++) { int c = wsum[w]; wsum[w] = acc; acc += c; }
            sbase = atomicAdd(&g_count, acc);         // reserve output slice
        }
        __syncthreads();
        int off = sbase + wsum[warp] + (x - cnt);
#pragma unroll
        for (int i = 0; i < 4; i++)
            if (v[i] != 0.0f) g_indices[off++] = base + i;
        __threadfence();
        if (tid == 0) atomicAdd((int*)&g_ready, 1);
    }

    // ================= Wait for compaction =================
    if (tid == 0) {
        while (*(volatile int*)&g_ready < COMPACT_BLOCKS) __nanosleep(64);
        __threadfence();
        s_n = *(volatile int*)&g_count;
    }
    __syncthreads();
    const int n = s_n;

    // ================= Phase B: stage indices + gather 4 rows =============
    const int n_s = (n < SMEM_IDX_CAP) ? n : SMEM_IDX_CAP;
    for (int k = tid; k < n_s; k += THREADS) buf[k] = g_indices[k];
    __syncthreads();

    const int r = bid * ROWS_PER_BLOCK;
    const float* __restrict__ row0 = conn + (size_t)r * INPUT_SIZE;
    const float* __restrict__ row1 = row0 + INPUT_SIZE;
    const float* __restrict__ row2 = row1 + INPUT_SIZE;
    const float* __restrict__ row3 = row2 + INPUT_SIZE;

    float a[4] = {0.f,0.f,0.f,0.f}, b[4] = {0.f,0.f,0.f,0.f};
    float c_[4] = {0.f,0.f,0.f,0.f}, d_[4] = {0.f,0.f,0.f,0.f};
    int k = tid;
    for (; k + 3 * THREADS < n_s; k += 4 * THREADS) {
        int i0 = buf[k];
        int i1 = buf[k +     THREADS];
        int i2 = buf[k + 2 * THREADS];
        int i3 = buf[k + 3 * THREADS];
        a[0] += __ldcs(row0 + i0);  b[0] += __ldcs(row1 + i0);
        c_[0] += __ldcs(row2 + i0); d_[0] += __ldcs(row3 + i0);
        a[1] += __ldcs(row0 + i1);  b[1] += __ldcs(row1 + i1);
        c_[1] += __ldcs(row2 + i1); d_[1] += __ldcs(row3 + i1);
        a[2] += __ldcs(row0 + i2);  b[2] += __ldcs(row1 + i2);
        c_[2] += __ldcs(row2 + i2); d_[2] += __ldcs(row3 + i2);
        a[3] += __ldcs(row0 + i3);  b[3] += __ldcs(row1 + i3);
        c_[3] += __ldcs(row2 + i3); d_[3] += __ldcs(row3 + i3);
    }
    for (; k < n_s; k += THREADS) {
        int i = buf[k];
        a[0] += __ldcs(row0 + i);  b[0] += __ldcs(row1 + i);
        c_[0] += __ldcs(row2 + i); d_[0] += __ldcs(row3 + i);
    }
    for (int k2 = SMEM_IDX_CAP + tid; k2 < n; k2 += THREADS) {  // safety tail
        int i = g_indices[k2];
        a[0] += __ldcs(row0 + i);  b[0] += __ldcs(row1 + i);
        c_[0] += __ldcs(row2 + i); d_[0] += __ldcs(row3 + i);
    }
    float sa = (a[0] + a[1]) + (a[2] + a[3]);
    float sb = (b[0] + b[1]) + (b[2] + b[3]);
    float sc = (c_[0] + c_[1]) + (c_[2] + c_[3]);
    float sd = (d_[0] + d_[1]) + (d_[2] + d_[3]);

#pragma unroll
    for (int dd = 16; dd; dd >>= 1) {
        sa += __shfl_down_sync(0xffffffffu, sa, dd);
        sb += __shfl_down_sync(0xffffffffu, sb, dd);
        sc += __shfl_down_sync(0xffffffffu, sc, dd);
        sd += __shfl_down_sync(0xffffffffu, sd, dd);
    }
    if (lane == 0) {
        wred[warp]      = sa;  wred[8 + warp]  = sb;
        wred[16 + warp] = sc;  wred[24 + warp] = sd;
    }
    __syncthreads();

    if (tid == 0) {
        float t0 = 0.f, t1 = 0.f, t2 = 0.f, t3 = 0.f;
#pragma unroll
        for (int w = 0; w < 8; w++) {
            t0 += wred[w]; t1 += wred[8 + w]; t2 += wred[16 + w]; t3 += wred[24 + w];
        }
        g_boosted[r]     = t0 * __ldg(&boost[r]);
        g_boosted[r + 1] = t1 * __ldg(&boost[r + 1]);
        g_boosted[r + 2] = t2 * __ldg(&boost[r + 2]);
        g_boosted[r + 3] = t3 * __ldg(&boost[r + 3]);
        __threadfence();
        int ticket = atomicAdd(&g_done, 1);
        s_elected = (ticket == NBLOCKS - 1) ? 1 : 0;
    }
    __syncthreads();

    // ================= Phase C: top-k (elected block only) =================
    if (s_elected) {
        if (tid == 0) __threadfence();   // acquire: see all g_boosted writes
        __syncthreads();

        // Load my 16 columns (contiguous, coalesced, L2 path).
        const int cbase = tid * 16;
        float vals[16];
        int   iv[16];
        const float4* gb4 = reinterpret_cast<const float4*>(g_boosted);
#pragma unroll
        for (int i = 0; i < 4; i++) {
            float4 f = __ldcg(&gb4[tid * 4 + i]);
            vals[4*i+0] = f.x; vals[4*i+1] = f.y;
            vals[4*i+2] = f.z; vals[4*i+3] = f.w;
        }
#pragma unroll
        for (int i = 0; i < 16; i++) {
            int t = (int)vals[i];                      // exact small integers
            iv[i] = (t < HIST_BINS) ? t : (HIST_BINS - 1);
        }

        // Zero histogram, then populate.
#pragma unroll
        for (int i = 0; i < 16; i++) buf[tid * 16 + i] = 0;
        __syncthreads();
#pragma unroll
        for (int i = 0; i < 16; i++) atomicAdd(&buf[iv[i]], 1);
        __syncthreads();

        // Per-thread bin-sum over owned bins [16*tid, 16*tid+16).
        int s = 0;
#pragma unroll
        for (int i = 0; i < 16; i++) s += buf[tid * 16 + i];

        // Suffix scan over thread bin-sums: above = sum of bins owned by
        // higher tids. Reverse into scan_tmp, exclusive prefix scan, map back.
        scan_tmp[255 - tid] = s;
        __syncthreads();
        {
            int x = scan_tmp[tid];
#pragma unroll
            for (int d = 1; d < 32; d <<= 1) {
                int y = __shfl_up_sync(0xffffffffu, x, d);
                if (lane >= d) x += y;                 // inclusive warp scan
            }
            if (lane == 31) wsum[warp] = x;
            __syncthreads();
            if (tid == 0) {
                int acc = 0;
#pragma unroll
                for (int w = 0; w < 8; w++) { int c = wsum[w]; wsum[w] = acc; acc += c; }
            }
            __syncthreads();
            int excl = wsum[warp] + x - scan_tmp[tid];  // exclusive prefix @tid
            __syncthreads();
            scan_tmp[255 - tid] = excl;                 // above for thread 255-tid
        }
        __syncthreads();
        int above = scan_tmp[tid];

        // Locate threshold: T is the unique bin with GE >= K > GT.
        {
            int running = above;                        // #{v > (my top bin)}
            for (int bin = tid * 16 + 15; bin >= tid * 16; --bin) {
                int cb = buf[bin];
                if (running + cb >= NUM_ACTIVE && running < NUM_ACTIVE) {
                    sT = bin;
                    sR = NUM_ACTIVE - running;          // ties to take, in index order
                }
                running += cb;
            }
        }
        __syncthreads();
        const int T = sT, R = sR;

        // Stable tie prefix: exclusive scan of per-thread equality counts.
        int eq = 0;
#pragma unroll
        for (int i = 0; i < 16; i++) eq += (iv[i] == T) ? 1 : 0;
        {
            int x = eq;
#pragma unroll
            for (int d = 1; d < 32; d <<= 1) {
                int y = __shfl_up_sync(0xffffffffu, x, d);
                if (lane >= d) x += y;
            }
            if (lane == 31) wsum[warp] = x;
            __syncthreads();
            if (tid == 0) {
                int acc = 0;
#pragma unroll
                for (int w = 0; w < 8; w++) { int c = wsum[w]; wsum[w] = acc; acc += c; }
            }
            __syncthreads();
            scan_tmp[tid] = wsum[warp] + x - eq;        // exclusive prefix
        }
        __syncthreads();

        // Decide winners and write both output segments (float4 stores).
        {
            int run = scan_tmp[tid];
            float mk[16], mv[16];
#pragma unroll
            for (int i = 0; i < 16; i++) {
                bool win;
                if (iv[i] > T)       win = true;
                else if (iv[i] == T) { win = (run < R); run++; }
                else                 win = false;
                mk[i] = win ? 1.0f    : 0.0f;
                mv[i] = win ? vals[i] : 0.0f;
            }
            float4* o0 = reinterpret_cast<float4*>(out + cbase);
            float4* o1 = reinterpret_cast<float4*>(out + NUM_COLS + cbase);
#pragma unroll
            for (int i = 0; i < 4; i++) {
                o0[i] = make_float4(mk[4*i], mk[4*i+1], mk[4*i+2], mk[4*i+3]);
                o1[i] = make_float4(mv[4*i], mv[4*i+1], mv[4*i+2], mv[4*i+3]);
            }
        }

        // Reset scratch for the next graph replay.
        if (tid == 0) { g_count = 0; g_ready = 0; g_done = 0; }
    }
}

// ---------------------------------------------------------------------------
extern "C" void kernel_launch(void* const* d_in, const int* in_sizes, int n_in,
                              void* d_out, int out_size) {
    const float* inp   = nullptr;
    const float* conn  = nullptr;
    const float* boost = nullptr;
    for (int i = 0; i < n_in; i++) {
        if (in_sizes[i] == INPUT_SIZE)      inp   = (const float*)d_in[i];
        else if (in_sizes[i] == NUM_COLS)   boost = (const float*)d_in[i];
        else                                conn  = (const float*)d_in[i];
    }
    float* out = (float*)d_out;
    (void)out_size; (void)n_in;

    fused_kernel<<<NBLOCKS, THREADS>>>(inp, conn, boost, out);
}

// round 8
// speedup vs baseline: 1.0865x; 1.0055x over previous
#include <cuda_runtime.h>

#define INPUT_SIZE     32768
#define NUM_COLS       4096
#define NUM_ACTIVE     82
#define THREADS        256
#define ROWS_PER_BLOCK 4
#define NBLOCKS        (NUM_COLS / ROWS_PER_BLOCK)   // 1024
#define COMPACT_BLOCKS 128
#define SMEM_IDX_CAP   2048
#define HIST_BINS      2048

// Scratch (allocation-free rule). Zero-initialized at module load; reset by
// the elected block at the end of each call -> graph replays deterministic.
__device__ int          g_count;
__device__ volatile int g_ready;
__device__ int          g_done;
__device__ int          g_indices[INPUT_SIZE];
__device__ float        g_boosted[NUM_COLS];

// ---------------------------------------------------------------------------
// ONE fused kernel:
//   Phase A (blocks 0..127): ballot-compact on-bit indices of input_vector
//     (atomic slice reservation; order nondeterministic, output invariant
//      since all downstream sums are exact small-integer commutative sums).
//   Phase B (all blocks): spin on flag, stage indices in SMEM, gather 4 rows
//     each with 16 independent load streams, block-reduce, write g_boosted.
//   Phase C (last-finishing block): 2048-bin histogram top-k over the exact
//     integer overlaps; stable tie-break by column index == jax.lax.top_k
//     order; writes both output segments; resets scratch.
// ---------------------------------------------------------------------------
__global__ __launch_bounds__(THREADS)
void fused_kernel(const float* __restrict__ in,
                  const float* __restrict__ conn,
                  const float* __restrict__ boost,
                  float* __restrict__ out) {
    __shared__ int   buf[HIST_BINS];     // phase B: sidx; phase C: histogram
    __shared__ int   s_n;
    __shared__ int   wsum[8];
    __shared__ int   sbase;
    __shared__ float wred[32];
    __shared__ int   s_elected;
    __shared__ int   sT, sR;
    __shared__ int   scan_tmp[THREADS];

    const int tid  = threadIdx.x;
    const int bid  = blockIdx.x;
    const int lane = tid & 31;
    const int warp = tid >> 5;

    // ================= Phase A: compaction (blocks 0..127) ================
    if (bid < COMPACT_BLOCKS) {
        const int idx = bid * 256 + tid;
        const bool on = (in[idx] != 0.0f);
        const unsigned m = __ballot_sync(0xffffffffu, on);
        if (lane == 0) wsum[warp] = __popc(m);
        __syncthreads();
        if (tid == 0) {
            int acc = 0;
#pragma unroll
            for (int w = 0; w < 8; w++) { int c = wsum[w]; wsum[w] = acc; acc += c; }
            sbase = atomicAdd(&g_count, acc);         // reserve output slice
        }
        __syncthreads();
        if (on) {
            const int pos = sbase + wsum[warp] + __popc(m & ((1u << lane) - 1u));
            g_indices[pos] = idx;
        }
        __threadfence();                 // every thread publishes its store
        __syncthreads();                 // ... before the block signals
        if (tid == 0) atomicAdd((int*)&g_ready, 1);
    }

    // ================= Wait for compaction =================
    if (tid == 0) {
        while (*(volatile int*)&g_ready < COMPACT_BLOCKS) __nanosleep(64);
        __threadfence();
        s_n = *(volatile int*)&g_count;
    }
    __syncthreads();
    const int n = s_n;

    // ================= Phase B: stage indices + gather 4 rows =============
    const int n_s = (n < SMEM_IDX_CAP) ? n : SMEM_IDX_CAP;
    for (int k = tid; k < n_s; k += THREADS) buf[k] = g_indices[k];
    __syncthreads();

    const int r = bid * ROWS_PER_BLOCK;
    const float* __restrict__ row0 = conn + (size_t)r * INPUT_SIZE;
    const float* __restrict__ row1 = row0 + INPUT_SIZE;
    const float* __restrict__ row2 = row1 + INPUT_SIZE;
    const float* __restrict__ row3 = row2 + INPUT_SIZE;

    float a[4] = {0.f,0.f,0.f,0.f}, b[4] = {0.f,0.f,0.f,0.f};
    float c_[4] = {0.f,0.f,0.f,0.f}, d_[4] = {0.f,0.f,0.f,0.f};
    int k = tid;
    for (; k + 3 * THREADS < n_s; k += 4 * THREADS) {
        int i0 = buf[k];
        int i1 = buf[k +     THREADS];
        int i2 = buf[k + 2 * THREADS];
        int i3 = buf[k + 3 * THREADS];
        a[0] += __ldcs(row0 + i0);  b[0] += __ldcs(row1 + i0);
        c_[0] += __ldcs(row2 + i0); d_[0] += __ldcs(row3 + i0);
        a[1] += __ldcs(row0 + i1);  b[1] += __ldcs(row1 + i1);
        c_[1] += __ldcs(row2 + i1); d_[1] += __ldcs(row3 + i1);
        a[2] += __ldcs(row0 + i2);  b[2] += __ldcs(row1 + i2);
        c_[2] += __ldcs(row2 + i2); d_[2] += __ldcs(row3 + i2);
        a[3] += __ldcs(row0 + i3);  b[3] += __ldcs(row1 + i3);
        c_[3] += __ldcs(row2 + i3); d_[3] += __ldcs(row3 + i3);
    }
    for (; k < n_s; k += THREADS) {
        int i = buf[k];
        a[0] += __ldcs(row0 + i);  b[0] += __ldcs(row1 + i);
        c_[0] += __ldcs(row2 + i); d_[0] += __ldcs(row3 + i);
    }
    for (int k2 = SMEM_IDX_CAP + tid; k2 < n; k2 += THREADS) {  // safety tail
        int i = g_indices[k2];
        a[0] += __ldcs(row0 + i);  b[0] += __ldcs(row1 + i);
        c_[0] += __ldcs(row2 + i); d_[0] += __ldcs(row3 + i);
    }
    float sa = (a[0] + a[1]) + (a[2] + a[3]);
    float sb = (b[0] + b[1]) + (b[2] + b[3]);
    float sc = (c_[0] + c_[1]) + (c_[2] + c_[3]);
    float sd = (d_[0] + d_[1]) + (d_[2] + d_[3]);

#pragma unroll
    for (int dd = 16; dd; dd >>= 1) {
        sa += __shfl_down_sync(0xffffffffu, sa, dd);
        sb += __shfl_down_sync(0xffffffffu, sb, dd);
        sc += __shfl_down_sync(0xffffffffu, sc, dd);
        sd += __shfl_down_sync(0xffffffffu, sd, dd);
    }
    if (lane == 0) {
        wred[warp]      = sa;  wred[8 + warp]  = sb;
        wred[16 + warp] = sc;  wred[24 + warp] = sd;
    }
    __syncthreads();

    if (tid == 0) {
        float t0 = 0.f, t1 = 0.f, t2 = 0.f, t3 = 0.f;
#pragma unroll
        for (int w = 0; w < 8; w++) {
            t0 += wred[w]; t1 += wred[8 + w]; t2 += wred[16 + w]; t3 += wred[24 + w];
        }
        g_boosted[r]     = t0 * __ldg(&boost[r]);
        g_boosted[r + 1] = t1 * __ldg(&boost[r + 1]);
        g_boosted[r + 2] = t2 * __ldg(&boost[r + 2]);
        g_boosted[r + 3] = t3 * __ldg(&boost[r + 3]);
        __threadfence();
        int ticket = atomicAdd(&g_done, 1);
        s_elected = (ticket == NBLOCKS - 1) ? 1 : 0;
    }
    __syncthreads();

    // ================= Phase C: top-k (elected block only) =================
    if (s_elected) {
        if (tid == 0) __threadfence();   // acquire: see all g_boosted writes
        __syncthreads();

        // Single load of my 16 contiguous columns (L2 path, coalesced).
        const int cbase = tid * 16;
        float va[16];
        const float4* gb4 = reinterpret_cast<const float4*>(g_boosted);
#pragma unroll
        for (int i = 0; i < 4; i++) {
            float4 f = __ldcg(&gb4[tid * 4 + i]);
            va[4*i+0] = f.x; va[4*i+1] = f.y;
            va[4*i+2] = f.z; va[4*i+3] = f.w;
        }

        // Zero histogram (8 bins/thread), then populate.
#pragma unroll
        for (int i = 0; i < 8; i++) buf[tid * 8 + i] = 0;
        __syncthreads();
#pragma unroll
        for (int i = 0; i < 16; i++) {
            int t = (int)va[i];                       // exact small integers
            if (t >= HIST_BINS) t = HIST_BINS - 1;
            atomicAdd(&buf[t], 1);
        }
        __syncthreads();

        // Per-thread bin-sum over owned bins [8*tid, 8*tid+8).
        int s = 0;
#pragma unroll
        for (int i = 0; i < 8; i++) s += buf[tid * 8 + i];

        // Suffix scan: above = sum of bins owned by higher tids.
        scan_tmp[255 - tid] = s;
        __syncthreads();
        {
            int x = scan_tmp[tid];
#pragma unroll
            for (int d = 1; d < 32; d <<= 1) {
                int y = __shfl_up_sync(0xffffffffu, x, d);
                if (lane >= d) x += y;                // inclusive warp scan
            }
            if (lane == 31) wsum[warp] = x;
            __syncthreads();
            if (tid == 0) {
                int acc = 0;
#pragma unroll
                for (int w = 0; w < 8; w++) { int c = wsum[w]; wsum[w] = acc; acc += c; }
            }
            __syncthreads();
            int excl = wsum[warp] + x - scan_tmp[tid];
            __syncthreads();
            scan_tmp[255 - tid] = excl;
        }
        __syncthreads();
        const int above = scan_tmp[tid];

        // Locate threshold bin T (unique: GE >= K > GT) and residue R.
        {
            int running = above;
            for (int bin = tid * 8 + 7; bin >= tid * 8; --bin) {
                int cb = buf[bin];
                if (running < NUM_ACTIVE && running + cb >= NUM_ACTIVE) {
                    sT = bin;
                    sR = NUM_ACTIVE - running;        // ties to take, index order
                }
                running += cb;
            }
        }
        __syncthreads();
        const int T = sT, R = sR;

        // Stable tie prefix: ascending exclusive scan of per-thread eq counts.
        int eq = 0;
#pragma unroll
        for (int i = 0; i < 16; i++) {
            int t = (int)va[i];
            if (t >= HIST_BINS) t = HIST_BINS - 1;
            eq += (t == T) ? 1 : 0;
        }
        int run;
        {
            int x = eq;
#pragma unroll
            for (int d = 1; d < 32; d <<= 1) {
                int y = __shfl_up_sync(0xffffffffu, x, d);
                if (lane >= d) x += y;
            }
            if (lane == 31) wsum[warp] = x;
            __syncthreads();
            if (tid == 0) {
                int acc = 0;
#pragma unroll
                for (int w = 0; w < 8; w++) { int c = wsum[w]; wsum[w] = acc; acc += c; }
            }
            __syncthreads();
            run = wsum[warp] + x - eq;                // exclusive prefix
        }

        // Decide winners, write both output segments (float4 stores).
        {
            float mk[16], mv[16];
#pragma unroll
            for (int i = 0; i < 16; i++) {
                int t = (int)va[i];
                if (t >= HIST_BINS) t = HIST_BINS - 1;
                bool win;
                if (t > T)       win = true;
                else if (t == T) { win = (run < R); run++; }
                else             win = false;
                mk[i] = win ? 1.0f  : 0.0f;
                mv[i] = win ? va[i] : 0.0f;
            }
            float4* o0 = reinterpret_cast<float4*>(out + cbase);
            float4* o1 = reinterpret_cast<float4*>(out + NUM_COLS + cbase);
#pragma unroll
            for (int i = 0; i < 4; i++) {
                o0[i] = make_float4(mk[4*i], mk[4*i+1], mk[4*i+2], mk[4*i+3]);
                o1[i] = make_float4(mv[4*i], mv[4*i+1], mv[4*i+2], mv[4*i+3]);
            }
        }

        // Reset scratch for the next graph replay.
        if (tid == 0) { g_count = 0; g_ready = 0; g_done = 0; }
    }
}

// ---------------------------------------------------------------------------
extern "C" void kernel_launch(void* const* d_in, const int* in_sizes, int n_in,
                              void* d_out, int out_size) {
    const float* inp   = nullptr;
    const float* conn  = nullptr;
    const float* boost = nullptr;
    for (int i = 0; i < n_in; i++) {
        if (in_sizes[i] == INPUT_SIZE)      inp   = (const float*)d_in[i];
        else if (in_sizes[i] == NUM_COLS)   boost = (const float*)d_in[i];
        else                                conn  = (const float*)d_in[i];
    }
    float* out = (float*)d_out;
    (void)out_size; (void)n_in;

    fused_kernel<<<NBLOCKS, THREADS>>>(inp, conn, boost, out);
}